// round 1
// baseline (speedup 1.0000x reference)
#include <cuda_runtime.h>
#include <math.h>

#define HID 1024
#define EMB 1024
#define MAXLEN 4096
#define VOCAB 50257

// ---------------- device scratch (no allocations allowed) ----------------
__device__ float g_hnew[HID];
__device__ float g_cnew[HID];
__device__ float g_scores[MAXLEN];
__device__ float g_ctx_part[128 * HID];
__device__ float g_ctx[HID];
__device__ float g_hid[HID];
__device__ float g_lse_m[256];
__device__ float g_lse_l[256];

__device__ __forceinline__ float warp_sum(float v) {
#pragma unroll
    for (int o = 16; o; o >>= 1) v += __shfl_down_sync(0xffffffffu, v, o);
    return v;
}

__device__ __forceinline__ float sigmoidf(float x) { return 1.f / (1.f + expf(-x)); }

// ---------------- K1: gates GEMV (W_ih@x + W_hh@h + biases) + LSTM pointwise ----------------
// one warp per hidden index j: computes all 4 gate rows (j, j+1024, j+2048, j+3072)
__global__ void k1_lstm(const float* __restrict__ W_ih, const float* __restrict__ W_hh,
                        const float* __restrict__ b_ih, const float* __restrict__ b_hh,
                        const float* __restrict__ x, const float* __restrict__ h,
                        const float* __restrict__ c, float* __restrict__ out_tail) {
    __shared__ __align__(16) float sx[EMB];
    __shared__ __align__(16) float sh[HID];
    for (int k = threadIdx.x; k < EMB; k += blockDim.x) sx[k] = x[k];
    for (int k = threadIdx.x; k < HID; k += blockDim.x) sh[k] = h[k];
    __syncthreads();

    int j = (blockIdx.x * blockDim.x + threadIdx.x) >> 5;
    int lane = threadIdx.x & 31;
    if (j >= HID) return;

    const float4* x4 = (const float4*)sx;
    const float4* h4 = (const float4*)sh;
    float acc[4];
#pragma unroll
    for (int g = 0; g < 4; g++) {
        const float4* rW = (const float4*)(W_ih + (size_t)(g * HID + j) * EMB);
        const float4* rU = (const float4*)(W_hh + (size_t)(g * HID + j) * HID);
        float a = 0.f;
#pragma unroll
        for (int k = lane; k < EMB / 4; k += 32) {
            float4 w = rW[k], xv = x4[k];
            a += w.x * xv.x + w.y * xv.y + w.z * xv.z + w.w * xv.w;
            float4 u = rU[k], hv = h4[k];
            a += u.x * hv.x + u.y * hv.y + u.z * hv.z + u.w * hv.w;
        }
        acc[g] = warp_sum(a);
    }
    if (lane == 0) {
        float gi = acc[0] + b_ih[j]            + b_hh[j];
        float gf = acc[1] + b_ih[HID + j]      + b_hh[HID + j];
        float gg = acc[2] + b_ih[2 * HID + j]  + b_hh[2 * HID + j];
        float go = acc[3] + b_ih[3 * HID + j]  + b_hh[3 * HID + j];
        float ig = sigmoidf(gi);
        float fg = sigmoidf(gf);
        float gt = tanhf(gg);
        float og = sigmoidf(go);
        float cn = fg * c[j] + ig * gt;
        float hn = og * tanhf(cn);
        g_cnew[j] = cn;
        g_hnew[j] = hn;
        out_tail[j] = hn;          // h_new at out[VOCAB .. VOCAB+HID)
        out_tail[HID + j] = cn;    // c_new at out[VOCAB+HID .. VOCAB+2*HID)
    }
}

// ---------------- K2: scores[t] = dot(A[t,:], h_new), t in [0,4096) ----------------
__global__ void k2_scores(const float* __restrict__ A) {
    __shared__ __align__(16) float sh[HID];
    for (int k = threadIdx.x; k < HID; k += blockDim.x) sh[k] = g_hnew[k];
    __syncthreads();

    int t = (blockIdx.x * blockDim.x + threadIdx.x) >> 5;
    int lane = threadIdx.x & 31;
    if (t >= MAXLEN) return;

    const float4* r = (const float4*)(A + (size_t)t * HID);
    const float4* h4 = (const float4*)sh;
    float a = 0.f;
#pragma unroll
    for (int k = lane; k < HID / 4; k += 32) {
        float4 v = r[k], hv = h4[k];
        a += v.x * hv.x + v.y * hv.y + v.z * hv.z + v.w * hv.w;
    }
    a = warp_sum(a);
    if (lane == 0) g_scores[t] = a;
}

// ---------------- K3: ctx partials; each block recomputes softmax stats (deterministic) ----------------
// grid 128 blocks x 512 threads; block b handles t in [b*32, b*32+32)
__global__ void k3_ctx_part(const float* __restrict__ A) {
    __shared__ float red[512];
    __shared__ float w_s[32];
    int tid = threadIdx.x;

    // block-wide max over all 4096 scores
    float m = -INFINITY;
    for (int t = tid; t < MAXLEN; t += 512) m = fmaxf(m, g_scores[t]);
    red[tid] = m;
    __syncthreads();
    for (int s = 256; s > 0; s >>= 1) {
        if (tid < s) red[tid] = fmaxf(red[tid], red[tid + s]);
        __syncthreads();
    }
    m = red[0];
    __syncthreads();

    // block-wide sum of exp
    float l = 0.f;
    for (int t = tid; t < MAXLEN; t += 512) l += expf(g_scores[t] - m);
    red[tid] = l;
    __syncthreads();
    for (int s = 256; s > 0; s >>= 1) {
        if (tid < s) red[tid] += red[tid + s];
        __syncthreads();
    }
    float inv_l = 1.f / red[0];
    __syncthreads();

    int t0 = blockIdx.x * 32;
    if (tid < 32) w_s[tid] = expf(g_scores[t0 + tid] - m) * inv_l;
    __syncthreads();

    float a0 = 0.f, a1 = 0.f;
#pragma unroll 4
    for (int t = 0; t < 32; t++) {
        const float* row = A + (size_t)(t0 + t) * HID;
        float w = w_s[t];
        a0 += row[tid] * w;
        a1 += row[tid + 512] * w;
    }
    g_ctx_part[blockIdx.x * HID + tid] = a0;
    g_ctx_part[blockIdx.x * HID + tid + 512] = a1;
}

// ---------------- K3b: reduce ctx partials (deterministic order) ----------------
__global__ void k3b_ctx_reduce() {
    int d = blockIdx.x * blockDim.x + threadIdx.x;
    float s = 0.f;
#pragma unroll 8
    for (int b = 0; b < 128; b++) s += g_ctx_part[b * HID + d];
    g_ctx[d] = s;
}

// ---------------- K4: fc1 GEMV: hid[i] = fc1_w[i,:] @ [ctx; h_new] + fc1_b[i] ----------------
__global__ void k4_fc1(const float* __restrict__ fc1_w, const float* __restrict__ fc1_b) {
    __shared__ __align__(16) float sc[2 * HID];
    for (int k = threadIdx.x; k < HID; k += blockDim.x) {
        sc[k] = g_ctx[k];
        sc[HID + k] = g_hnew[k];
    }
    __syncthreads();

    int i = (blockIdx.x * blockDim.x + threadIdx.x) >> 5;
    int lane = threadIdx.x & 31;
    if (i >= HID) return;

    const float4* r = (const float4*)(fc1_w + (size_t)i * 2 * HID);
    const float4* c4 = (const float4*)sc;
    float a = 0.f;
#pragma unroll
    for (int k = lane; k < (2 * HID) / 4; k += 32) {
        float4 v = r[k], cv = c4[k];
        a += v.x * cv.x + v.y * cv.y + v.z * cv.z + v.w * cv.w;
    }
    a = warp_sum(a);
    if (lane == 0) g_hid[i] = a + fc1_b[i];
}

// ---------------- K5: fc2 GEMV: out[i] = fc2_w[i,:] @ hid + fc2_b[i] ----------------
__global__ void k5_fc2(const float* __restrict__ fc2_w, const float* __restrict__ fc2_b,
                       float* __restrict__ out) {
    __shared__ __align__(16) float shd[HID];
    for (int k = threadIdx.x; k < HID; k += blockDim.x) shd[k] = g_hid[k];
    __syncthreads();

    int i = (blockIdx.x * blockDim.x + threadIdx.x) >> 5;
    if (i >= VOCAB) return;
    int lane = threadIdx.x & 31;

    const float4* r = (const float4*)(fc2_w + (size_t)i * HID);
    const float4* h4 = (const float4*)shd;
    float a = 0.f;
#pragma unroll
    for (int k = lane; k < HID / 4; k += 32) {
        float4 v = r[k], hv = h4[k];
        a += v.x * hv.x + v.y * hv.y + v.z * hv.z + v.w * hv.w;
    }
    a = warp_sum(a);
    if (lane == 0) out[i] = a + fc2_b[i];
}

// ---------------- K6: log-sum-exp partials over logits ----------------
// grid 256 x 256: each thread covers <=1 element (50257 < 65536)
__global__ void k6_lse_part(const float* __restrict__ out) {
    __shared__ float sm[256];
    __shared__ float sl[256];
    int idx = blockIdx.x * blockDim.x + threadIdx.x;
    float m = -INFINITY, l = 0.f;
    if (idx < VOCAB) { m = out[idx]; l = 1.f; }
    sm[threadIdx.x] = m;
    sl[threadIdx.x] = l;
    __syncthreads();
    for (int s = 128; s > 0; s >>= 1) {
        if (threadIdx.x < s) {
            float m1 = sm[threadIdx.x], l1 = sl[threadIdx.x];
            float m2 = sm[threadIdx.x + s], l2 = sl[threadIdx.x + s];
            float mm = fmaxf(m1, m2);
            float ll = (l1 > 0.f ? l1 * expf(m1 - mm) : 0.f) +
                       (l2 > 0.f ? l2 * expf(m2 - mm) : 0.f);
            sm[threadIdx.x] = mm;
            sl[threadIdx.x] = ll;
        }
        __syncthreads();
    }
    if (threadIdx.x == 0) {
        g_lse_m[blockIdx.x] = sm[0];
        g_lse_l[blockIdx.x] = sl[0];
    }
}

// ---------------- K7: combine lse partials + in-place logp = logit - lse ----------------
__global__ void k7_final(float* __restrict__ out) {
    __shared__ float sm[256];
    __shared__ float sl[256];
    int tid = threadIdx.x;
    sm[tid] = g_lse_m[tid];
    sl[tid] = g_lse_l[tid];
    __syncthreads();
    for (int s = 128; s > 0; s >>= 1) {
        if (tid < s) {
            float m1 = sm[tid], l1 = sl[tid];
            float m2 = sm[tid + s], l2 = sl[tid + s];
            float mm = fmaxf(m1, m2);
            float ll = (l1 > 0.f ? l1 * expf(m1 - mm) : 0.f) +
                       (l2 > 0.f ? l2 * expf(m2 - mm) : 0.f);
            sm[tid] = mm;
            sl[tid] = ll;
        }
        __syncthreads();
    }
    float lse = sm[0] + logf(sl[0]);
    int i = blockIdx.x * 256 + tid;
    if (i < VOCAB) out[i] -= lse;
}

// ---------------- launch ----------------
extern "C" void kernel_launch(void* const* d_in, const int* in_sizes, int n_in,
                              void* d_out, int out_size) {
    const float* attn  = (const float*)d_in[0];   // (4096, 1, 1024)
    const float* x     = (const float*)d_in[1];   // (1024,)
    const float* h     = (const float*)d_in[2];   // (1,1,1024)
    const float* c     = (const float*)d_in[3];   // (1,1,1024)
    const float* W_ih  = (const float*)d_in[4];   // (4096, 1024)
    const float* W_hh  = (const float*)d_in[5];   // (4096, 1024)
    const float* b_ih  = (const float*)d_in[6];   // (4096,)
    const float* b_hh  = (const float*)d_in[7];   // (4096,)
    const float* fc1_w = (const float*)d_in[8];   // (1024, 2048)
    const float* fc1_b = (const float*)d_in[9];   // (1024,)
    const float* fc2_w = (const float*)d_in[10];  // (50257, 1024)
    const float* fc2_b = (const float*)d_in[11];  // (50257,)
    float* out = (float*)d_out;

    // K1: 1024 warps (one per hidden j), 4 warps/block
    k1_lstm<<<256, 128>>>(W_ih, W_hh, b_ih, b_hh, x, h, c, out + VOCAB);
    // K2: 4096 warps (one per timestep)
    k2_scores<<<512, 256>>>(attn);
    // K3: 128 blocks x 512 threads, softmax stats recomputed per block
    k3_ctx_part<<<128, 512>>>(attn);
    // K3b: reduce 128 partials -> ctx[1024]
    k3b_ctx_reduce<<<4, 256>>>();
    // K4: fc1, 1024 warps
    k4_fc1<<<128, 256>>>(fc1_w, fc1_b);
    // K5: fc2, 50257 warps -> logits into d_out
    k5_fc2<<<(VOCAB + 7) / 8, 256>>>(fc2_w, fc2_b, out);
    // K6: 256 lse partials
    k6_lse_part<<<256, 256>>>(out);
    // K7: combine + subtract in place
    k7_final<<<(VOCAB + 255) / 256, 256>>>(out);
}